// round 3
// baseline (speedup 1.0000x reference)
#include <cuda_runtime.h>
#include <math.h>

// Problem constants
#define BB 4
#define SS 2048
#define HH 1024
#define RR 512
#define NHEAD 8
#define HDIM 64
#define NTOK 8192L   // B*S

// ---------------------------------------------------------------------------
// Scratch (static device globals; no allocation allowed)
// ---------------------------------------------------------------------------
__device__ float d_pooled[BB * HH];
__device__ float d_r[NTOK * RR];
__device__ float d_y[NTOK * RR];
__device__ float d_qkv[NTOK * 3 * RR];
__device__ float d_sc[(long)BB * NHEAD * SS * SS];   // 512 MB attention scores
__device__ float d_o[NTOK * RR];
__device__ float d_ff[NTOK * 4 * RR];
__device__ float d_reason[NTOK * HH];
__device__ float d_tmp[NTOK * HH];
__device__ float d_g[NTOK * HH];

// ---------------------------------------------------------------------------
// Generic tiled SGEMM: C = epi(alpha * A@B(^T) + bias + res)
//   128x128 block tile, BK=8, 256 threads, 8x8 per-thread microtile.
//   Batched via blockIdx.z: off = (z/zdiv)*s?o + (z%zdiv)*s?i
//   epi: 0 = none, 1 = relu, 2 = sigmoid
// ---------------------------------------------------------------------------
template <bool TB>
__global__ __launch_bounds__(256) void sgemm_kernel(
    const float* __restrict__ A, const float* __restrict__ Bm,
    const float* __restrict__ bias, const float* __restrict__ res,
    float* __restrict__ C,
    int M, int N, int K, int lda, int ldb, int ldc,
    long sAo, long sAi, long sBo, long sBi, long sCo, long sCi,
    int zdiv, float alpha, int epi)
{
    __shared__ float As[8][132];   // padded: conflict-free transpose store
    __shared__ float Bs[8][132];

    int zb = blockIdx.z / zdiv, zi = blockIdx.z % zdiv;
    A  += zb * sAo + zi * sAi;
    Bm += zb * sBo + zi * sBi;
    C  += zb * sCo + zi * sCi;

    int m0 = blockIdx.y * 128;
    int n0 = blockIdx.x * 128;
    int tid = threadIdx.x;
    int tx = tid & 15, ty = tid >> 4;

    float acc[8][8];
#pragma unroll
    for (int i = 0; i < 8; i++)
#pragma unroll
        for (int j = 0; j < 8; j++) acc[i][j] = 0.f;

    for (int kt = 0; kt < K; kt += 8) {
        // A tile: 128 rows x 8 k  -> As[k][m]
#pragma unroll
        for (int l = 0; l < 4; l++) {
            int i = tid + l * 256;
            int r = i >> 3, c = i & 7;
            int gm = m0 + r, gk = kt + c;
            As[c][r] = (gm < M && gk < K) ? A[(long)gm * lda + gk] : 0.f;
        }
        if (!TB) {
            // B tile: 8 k x 128 n -> Bs[k][n]
#pragma unroll
            for (int l = 0; l < 4; l++) {
                int i = tid + l * 256;
                int rr = i >> 7, cc = i & 127;
                int gk = kt + rr, gn = n0 + cc;
                Bs[rr][cc] = (gk < K && gn < N) ? Bm[(long)gk * ldb + gn] : 0.f;
            }
        } else {
            // B stored [N x K]; Bs[k][n] = B[n][k]
#pragma unroll
            for (int l = 0; l < 4; l++) {
                int i = tid + l * 256;
                int nn = i >> 3, kk2 = i & 7;
                int gn = n0 + nn, gk = kt + kk2;
                Bs[kk2][nn] = (gn < N && gk < K) ? Bm[(long)gn * ldb + gk] : 0.f;
            }
        }
        __syncthreads();

#pragma unroll
        for (int kk = 0; kk < 8; kk++) {
            float a[8], b[8];
            *(float4*)&a[0] = *(const float4*)&As[kk][ty * 8];
            *(float4*)&a[4] = *(const float4*)&As[kk][ty * 8 + 4];
            *(float4*)&b[0] = *(const float4*)&Bs[kk][tx * 8];
            *(float4*)&b[4] = *(const float4*)&Bs[kk][tx * 8 + 4];
#pragma unroll
            for (int i = 0; i < 8; i++)
#pragma unroll
                for (int j = 0; j < 8; j++)
                    acc[i][j] = fmaf(a[i], b[j], acc[i][j]);
        }
        __syncthreads();
    }

#pragma unroll
    for (int i = 0; i < 8; i++) {
        int gm = m0 + ty * 8 + i;
        if (gm >= M) continue;
#pragma unroll
        for (int j = 0; j < 8; j++) {
            int gn = n0 + tx * 8 + j;
            if (gn >= N) continue;
            float v = acc[i][j] * alpha;
            if (bias) v += bias[gn];
            if (res)  v += res[(long)gm * ldc + gn];
            if (epi == 1)      v = fmaxf(v, 0.f);
            else if (epi == 2) v = 1.f / (1.f + __expf(-v));
            C[(long)gm * ldc + gn] = v;
        }
    }
}

// ---------------------------------------------------------------------------
// Block reductions (256 threads)
// ---------------------------------------------------------------------------
__device__ __forceinline__ float blk_reduce_sum(float v) {
    __shared__ float sh[8];
    int t = threadIdx.x;
#pragma unroll
    for (int o = 16; o; o >>= 1) v += __shfl_down_sync(0xffffffffu, v, o);
    if ((t & 31) == 0) sh[t >> 5] = v;
    __syncthreads();
    if (t < 32) {
        float w = (t < 8) ? sh[t] : 0.f;
#pragma unroll
        for (int o = 4; o; o >>= 1) w += __shfl_down_sync(0xffffffffu, w, o);
        if (t == 0) sh[0] = w;
    }
    __syncthreads();
    float r = sh[0];
    __syncthreads();
    return r;
}

__device__ __forceinline__ float blk_reduce_max(float v) {
    __shared__ float sh[8];
    int t = threadIdx.x;
#pragma unroll
    for (int o = 16; o; o >>= 1) v = fmaxf(v, __shfl_down_sync(0xffffffffu, v, o));
    if ((t & 31) == 0) sh[t >> 5] = v;
    __syncthreads();
    if (t < 32) {
        float w = (t < 8) ? sh[t] : -1e30f;
#pragma unroll
        for (int o = 4; o; o >>= 1) w = fmaxf(w, __shfl_down_sync(0xffffffffu, w, o));
        if (t == 0) sh[0] = w;
    }
    __syncthreads();
    float r = sh[0];
    __syncthreads();
    return r;
}

// LayerNorm: one block (256 thr) per row
__global__ void ln_kernel(const float* __restrict__ x, const float* __restrict__ g,
                          const float* __restrict__ b, float* __restrict__ y, int D)
{
    long row = blockIdx.x;
    const float* xr = x + row * (long)D;
    float* yr = y + row * (long)D;
    float s = 0.f;
    for (int i = threadIdx.x; i < D; i += 256) s += xr[i];
    float mean = blk_reduce_sum(s) / (float)D;
    float vs = 0.f;
    for (int i = threadIdx.x; i < D; i += 256) { float d = xr[i] - mean; vs += d * d; }
    float var = blk_reduce_sum(vs) / (float)D;
    float rstd = rsqrtf(var + 1e-5f);
    for (int i = threadIdx.x; i < D; i += 256)
        yr[i] = (xr[i] - mean) * rstd * g[i] + b[i];
}

// Softmax over rows of length 2048; one block per row
__global__ void softmax_kernel(float* __restrict__ s)
{
    long row = blockIdx.x;
    float* p = s + row * 2048L;
    float v[8];
    float m = -1e30f;
#pragma unroll
    for (int l = 0; l < 8; l++) { v[l] = p[threadIdx.x + l * 256]; m = fmaxf(m, v[l]); }
    m = blk_reduce_max(m);
    float sum = 0.f;
#pragma unroll
    for (int l = 0; l < 8; l++) { v[l] = __expf(v[l] - m); sum += v[l]; }
    sum = blk_reduce_sum(sum);
    float inv = 1.f / sum;
#pragma unroll
    for (int l = 0; l < 8; l++) p[threadIdx.x + l * 256] = v[l] * inv;
}

// Pool: pooled[b][h] = mean_s hidden[b][s][h].  grid(H/256, B), block 256
__global__ void pool_mean_kernel(const float* __restrict__ hs, float* __restrict__ pooled)
{
    int b = blockIdx.y;
    int h = blockIdx.x * 256 + threadIdx.x;
    const float* p = hs + (long)b * SS * HH + h;
    float sum = 0.f;
    for (int s = 0; s < SS; s++) sum += p[(long)s * HH];
    pooled[b * HH + h] = sum * (1.f / SS);
}

// Complexity assessor MLP, single block of 256 threads
__global__ void ca_kernel(const float* __restrict__ pooled,
                          const float* __restrict__ w1, const float* __restrict__ b1,
                          const float* __restrict__ w2, const float* __restrict__ b2,
                          const float* __restrict__ w3, const float* __restrict__ b3,
                          float* __restrict__ scores_out)
{
    __shared__ float h1[BB][256];
    __shared__ float h2[BB][32];
    int t = threadIdx.x;
    for (int b = 0; b < BB; b++) {
        float acc = b1[t];
        for (int k = 0; k < HH; k++) acc = fmaf(pooled[b * HH + k], w1[k * 256 + t], acc);
        h1[b][t] = fmaxf(acc, 0.f);
    }
    __syncthreads();
    if (t < 32) {
        for (int b = 0; b < BB; b++) {
            float acc = b2[t];
            for (int k = 0; k < 256; k++) acc = fmaf(h1[b][k], w2[k * 32 + t], acc);
            h2[b][t] = fmaxf(acc, 0.f);
        }
    }
    __syncthreads();
    if (t < BB) {
        float acc = b3[0];
        for (int k = 0; k < 32; k++) acc = fmaf(h2[t][k], w3[k], acc);
        scores_out[t] = 1.f / (1.f + expf(-acc));
    }
}

// out = hidden + g * reasoned
__global__ void gate_out_kernel(const float* __restrict__ hs, const float* __restrict__ g,
                                const float* __restrict__ reasoned, float* __restrict__ out,
                                long n)
{
    long i = (long)blockIdx.x * 256 + threadIdx.x;
    if (i < n) out[i] = hs[i] + g[i] * reasoned[i];
}

// ---------------------------------------------------------------------------
// Host launch
// ---------------------------------------------------------------------------
static inline void gemm(const float* A, const float* B, const float* bias, const float* res,
                        float* C, int M, int N, int K, int lda, int ldb, int ldc,
                        long sAo, long sAi, long sBo, long sBi, long sCo, long sCi,
                        int Z, int zdiv, float alpha, int epi, bool tb)
{
    dim3 grid((N + 127) / 128, (M + 127) / 128, Z);
    if (tb)
        sgemm_kernel<true><<<grid, 256>>>(A, B, bias, res, C, M, N, K, lda, ldb, ldc,
                                          sAo, sAi, sBo, sBi, sCo, sCi, zdiv, alpha, epi);
    else
        sgemm_kernel<false><<<grid, 256>>>(A, B, bias, res, C, M, N, K, lda, ldb, ldc,
                                           sAo, sAi, sBo, sBi, sCo, sCi, zdiv, alpha, epi);
}

extern "C" void kernel_launch(void* const* d_in, const int* in_sizes, int n_in,
                              void* d_out, int out_size)
{
    const float* hs    = (const float*)d_in[0];
    const float* ca_w1 = (const float*)d_in[1];
    const float* ca_b1 = (const float*)d_in[2];
    const float* ca_w2 = (const float*)d_in[3];
    const float* ca_b2 = (const float*)d_in[4];
    const float* ca_w3 = (const float*)d_in[5];
    const float* ca_b3 = (const float*)d_in[6];
    const float* rp_w  = (const float*)d_in[7];
    const float* rp_b  = (const float*)d_in[8];
    const float* rn_g  = (const float*)d_in[9];
    const float* rn_b  = (const float*)d_in[10];
    const float* ln1_g = (const float*)d_in[11];
    const float* ln1_b = (const float*)d_in[12];
    const float* wqkv  = (const float*)d_in[13];
    const float* bqkv  = (const float*)d_in[14];
    const float* wo    = (const float*)d_in[15];
    const float* bo    = (const float*)d_in[16];
    const float* ln2_g = (const float*)d_in[17];
    const float* ln2_b = (const float*)d_in[18];
    const float* ff1_w = (const float*)d_in[19];
    const float* ff1_b = (const float*)d_in[20];
    const float* ff2_w = (const float*)d_in[21];
    const float* ff2_b = (const float*)d_in[22];
    const float* op_w  = (const float*)d_in[23];
    const float* op_b  = (const float*)d_in[24];
    const float* on_g  = (const float*)d_in[25];
    const float* on_b  = (const float*)d_in[26];
    const float* gw1   = (const float*)d_in[27];
    const float* gb1   = (const float*)d_in[28];
    const float* gw2   = (const float*)d_in[29];
    const float* gb2   = (const float*)d_in[30];

    float* out = (float*)d_out;
    float* cs  = out + NTOK * HH;   // complexity scores after the main output

    float *pooled, *r, *y, *qkv, *sc, *o, *ff, *reason, *tmp, *g;
    cudaGetSymbolAddress((void**)&pooled, d_pooled);
    cudaGetSymbolAddress((void**)&r,      d_r);
    cudaGetSymbolAddress((void**)&y,      d_y);
    cudaGetSymbolAddress((void**)&qkv,    d_qkv);
    cudaGetSymbolAddress((void**)&sc,     d_sc);
    cudaGetSymbolAddress((void**)&o,      d_o);
    cudaGetSymbolAddress((void**)&ff,     d_ff);
    cudaGetSymbolAddress((void**)&reason, d_reason);
    cudaGetSymbolAddress((void**)&tmp,    d_tmp);
    cudaGetSymbolAddress((void**)&g,      d_g);

    // 1) complexity assessor
    pool_mean_kernel<<<dim3(HH / 256, BB), 256>>>(hs, pooled);
    ca_kernel<<<1, 256>>>(pooled, ca_w1, ca_b1, ca_w2, ca_b2, ca_w3, ca_b3, cs);

    // 2) reasoning projection + pre-norm: r = LN(hs @ rp_w + rp_b)
    gemm(hs, rp_w, rp_b, nullptr, r, 8192, 512, 1024, 1024, 512, 512,
         0, 0, 0, 0, 0, 0, 1, 1, 1.f, 0, false);
    ln_kernel<<<8192, 256>>>(r, rn_g, rn_b, r, 512);

    // 3) attention: y = LN1(r); qkv = y@wqkv+b
    ln_kernel<<<8192, 256>>>(r, ln1_g, ln1_b, y, 512);
    gemm(y, wqkv, bqkv, nullptr, qkv, 8192, 1536, 512, 512, 1536, 1536,
         0, 0, 0, 0, 0, 0, 1, 1, 1.f, 0, false);

    // scores[b,h] = Q Kt / 8    (z = b*8+h, TB: K rows are key tokens)
    gemm(qkv, qkv + 512, nullptr, nullptr, sc, 2048, 2048, 64, 1536, 1536, 2048,
         (long)SS * 1536, 64, (long)SS * 1536, 64, (long)NHEAD * SS * SS, (long)SS * SS,
         BB * NHEAD, NHEAD, 0.125f, 0, true);
    softmax_kernel<<<BB * NHEAD * SS, 256>>>(sc);
    // o = attn @ V
    gemm(sc, qkv + 1024, nullptr, nullptr, o, 2048, 64, 2048, 2048, 1536, 512,
         (long)NHEAD * SS * SS, (long)SS * SS, (long)SS * 1536, 64, (long)SS * 512, 64,
         BB * NHEAD, NHEAD, 1.f, 0, false);
    // r = r + o@wo + bo
    gemm(o, wo, bo, r, r, 8192, 512, 512, 512, 512, 512,
         0, 0, 0, 0, 0, 0, 1, 1, 1.f, 0, false);

    // 4) FFN: r = r + relu(LN2(r)@ff1+b)@ff2+b
    ln_kernel<<<8192, 256>>>(r, ln2_g, ln2_b, y, 512);
    gemm(y, ff1_w, ff1_b, nullptr, ff, 8192, 2048, 512, 512, 2048, 2048,
         0, 0, 0, 0, 0, 0, 1, 1, 1.f, 1, false);
    gemm(ff, ff2_w, ff2_b, r, r, 8192, 512, 2048, 2048, 512, 512,
         0, 0, 0, 0, 0, 0, 1, 1, 1.f, 0, false);

    // 5) output projection + norm: reasoned = LN(r@op_w + op_b)
    gemm(r, op_w, op_b, nullptr, reason, 8192, 1024, 512, 512, 1024, 1024,
         0, 0, 0, 0, 0, 0, 1, 1, 1.f, 0, false);
    ln_kernel<<<8192, 256>>>(reason, on_g, on_b, reason, 1024);

    // 6) gate: g1 = relu(hs@gw1_top + reasoned@gw1_bot + gb1); g = sigmoid(g1@gw2+gb2)
    gemm(hs, gw1, gb1, nullptr, tmp, 8192, 1024, 1024, 1024, 1024, 1024,
         0, 0, 0, 0, 0, 0, 1, 1, 1.f, 0, false);
    gemm(reason, gw1 + (long)HH * HH, nullptr, tmp, tmp, 8192, 1024, 1024, 1024, 1024, 1024,
         0, 0, 0, 0, 0, 0, 1, 1, 1.f, 1, false);
    gemm(tmp, gw2, gb2, nullptr, g, 8192, 1024, 1024, 1024, 1024, 1024,
         0, 0, 0, 0, 0, 0, 1, 1, 1.f, 2, false);

    // 7) output = hs + g * reasoned
    gate_out_kernel<<<(int)((NTOK * HH + 255) / 256), 256>>>(hs, g, reason, out, NTOK * HH);
}

// round 8
// speedup vs baseline: 2.6837x; 2.6837x over previous
#include <cuda_runtime.h>
#include <cuda_bf16.h>
#include <cstdint>
#include <math.h>

typedef __nv_bfloat16 bf;

// Problem constants
#define BB 4
#define SS 2048
#define HH 1024
#define RR 512
#define NHEAD 8
#define HDIM 64
#define NTOK 8192L   // B*S

// ===========================================================================
// Baseline-PTX helpers (sm_80-era: ldmatrix / mma.sync / cp.async)
// ===========================================================================
__device__ __forceinline__ uint32_t smem_to_u32(const void* p) {
    uint32_t a;
    asm("{ .reg .u64 t; cvta.to.shared.u64 t, %1; cvt.u32.u64 %0, t; }" : "=r"(a) : "l"(p));
    return a;
}
__device__ __forceinline__ void ldm_x4(uint32_t* r, uint32_t addr) {
    asm volatile("ldmatrix.sync.aligned.m8n8.x4.shared.b16 {%0,%1,%2,%3}, [%4];"
                 : "=r"(r[0]), "=r"(r[1]), "=r"(r[2]), "=r"(r[3]) : "r"(addr));
}
__device__ __forceinline__ void mma_bf16(float* d, const uint32_t* a, const uint32_t* b) {
    asm volatile("mma.sync.aligned.m16n8k16.row.col.f32.bf16.bf16.f32 "
                 "{%0,%1,%2,%3}, {%4,%5,%6,%7}, {%8,%9}, {%0,%1,%2,%3};"
                 : "+f"(d[0]), "+f"(d[1]), "+f"(d[2]), "+f"(d[3])
                 : "r"(a[0]), "r"(a[1]), "r"(a[2]), "r"(a[3]), "r"(b[0]), "r"(b[1]));
}
#define CP_ASYNC16(dst, src) \
    asm volatile("cp.async.cg.shared.global [%0], [%1], 16;" :: "r"(dst), "l"(src))
#define CP_COMMIT() asm volatile("cp.async.commit_group;" ::: "memory")
#define CP_WAIT1()  asm volatile("cp.async.wait_group 1;" ::: "memory")
#define CP_WAIT0()  asm volatile("cp.async.wait_group 0;" ::: "memory")

// Swizzled smem offset: rows of 64B (32 bf16), 4x 16B chunks, XOR by (row>>1)&3
#define SWZ(row, c) ((uint32_t)((row) * 64 + (((c) ^ (((row) >> 1) & 3)) << 4)))

// ===========================================================================
// Scratch (static device globals; no allocation allowed)
// ===========================================================================
__device__ float d_pooled[BB * HH];
__device__ float d_r[NTOK * RR];
__device__ float d_sc[(long)BB * NHEAD * SS * SS];   // fp32 attention scores
__device__ float d_tmpf[NTOK * HH];
__device__ float d_g[NTOK * HH];
__device__ float d_reason[NTOK * HH];

__device__ bf d_hs_h[NTOK * HH],  d_hs_l[NTOK * HH];
__device__ bf d_y_h[NTOK * RR],   d_y_l[NTOK * RR];
__device__ bf d_qkv_h[NTOK * 3 * RR], d_qkv_l[NTOK * 3 * RR];
__device__ bf d_attn_h[(long)BB * NHEAD * SS * SS];
__device__ bf d_attn_l[(long)BB * NHEAD * SS * SS];
__device__ bf d_vt_h[(long)BB * NHEAD * HDIM * SS], d_vt_l[(long)BB * NHEAD * HDIM * SS];
__device__ bf d_o_h[NTOK * RR],   d_o_l[NTOK * RR];
__device__ bf d_ff_h[NTOK * 4 * RR], d_ff_l[NTOK * 4 * RR];
__device__ bf d_rs_h[NTOK * RR],  d_rs_l[NTOK * RR];
__device__ bf d_re_h[NTOK * HH],  d_re_l[NTOK * HH];
__device__ bf d_t2_h[NTOK * HH],  d_t2_l[NTOK * HH];
// transposed + split weights ([N,K] bf16)
__device__ bf d_rpT_h[RR * HH],       d_rpT_l[RR * HH];
__device__ bf d_qkvT_h[3 * RR * RR],  d_qkvT_l[3 * RR * RR];
__device__ bf d_woT_h[RR * RR],       d_woT_l[RR * RR];
__device__ bf d_ff1T_h[4 * RR * RR],  d_ff1T_l[4 * RR * RR];
__device__ bf d_ff2T_h[RR * 4 * RR],  d_ff2T_l[RR * 4 * RR];
__device__ bf d_opT_h[HH * RR],       d_opT_l[HH * RR];
__device__ bf d_g1T_h[HH * 2 * HH],   d_g1T_l[HH * 2 * HH];
__device__ bf d_g2T_h[HH * HH],       d_g2T_l[HH * HH];

// ===========================================================================
// Warp-MMA split-bf16 GEMM: D = Ah*Bh + Ah*Bl + Al*Bh (fp32 accum, HMMA)
//   A: [M,K] bf16 (K-major), B: [N,K] bf16 (K-major)
//   CTA tile 128 x BN, BK=32, 8 warps (2 x 4), warp tile 64 x BN/4.
//   cp.async 2-stage pipeline; swizzled smem; ldmatrix fragments.
//   Epilogue: v = D*alpha + bias + res; act(0/1 relu/2 sigmoid);
//             writes C fp32 and/or (Ch, Cl) split bf16.
// ===========================================================================
template <int BN>
__global__ void __launch_bounds__(256, 2) gemm_tc_kernel(
    const bf* __restrict__ Ah, const bf* __restrict__ Al,
    const bf* __restrict__ Bh, const bf* __restrict__ Bl,
    const float* __restrict__ bias, const float* __restrict__ res,
    float* __restrict__ C, bf* __restrict__ Ch, bf* __restrict__ Cl,
    int K, int lda, int ldb, int ldc,
    long sAo, long sAi, long sBo, long sBi, long sCo, long sCi, int zdiv,
    float alpha, int act)
{
    constexpr int WN  = BN / 4;       // warp n extent
    constexpr int WN8 = BN / 32;      // n8 tiles per warp
    constexpr int ATB = 128 * 64;     // 8192 B per A matrix per stage
    constexpr int BTB = BN * 64;      // B matrix bytes per stage
    constexpr int STG = 2 * ATB + 2 * BTB;

    extern __shared__ char smem[];
    uint32_t sb = smem_to_u32(smem);

    int tid = threadIdx.x, wid = tid >> 5, lane = tid & 31;
    int wm = wid & 1, wn = wid >> 1;

    long zb = blockIdx.z / zdiv, zi = blockIdx.z % zdiv;
    int m0 = blockIdx.y * 128, n0 = blockIdx.x * BN;
    const bf* gAh = Ah + zb * sAo + zi * sAi + (long)m0 * lda;
    const bf* gAl = Al + zb * sAo + zi * sAi + (long)m0 * lda;
    const bf* gBh = Bh + zb * sBo + zi * sBi + (long)n0 * ldb;
    const bf* gBl = Bl + zb * sBo + zi * sBi + (long)n0 * ldb;

    const int nc = K >> 5;   // 32-wide K chunks

    auto load_chunk = [&](int c, int s) {
        uint32_t base = sb + s * STG;
        long ko = (long)c << 5;
#pragma unroll
        for (int i = tid; i < 512; i += 256) {          // A: 128 rows x 4 chunks
            int r = i >> 2, q = i & 3;
            long go = (long)r * lda + ko + q * 8;
            uint32_t so = SWZ(r, q);
            CP_ASYNC16(base + so,       gAh + go);
            CP_ASYNC16(base + ATB + so, gAl + go);
        }
#pragma unroll
        for (int i = tid; i < BN * 4; i += 256) {       // B: BN rows x 4 chunks
            int r = i >> 2, q = i & 3;
            long go = (long)r * ldb + ko + q * 8;
            uint32_t so = SWZ(r, q);
            CP_ASYNC16(base + 2 * ATB + so,       gBh + go);
            CP_ASYNC16(base + 2 * ATB + BTB + so, gBl + go);
        }
    };

    float acc[4][WN8][4];
#pragma unroll
    for (int i = 0; i < 4; i++)
#pragma unroll
        for (int j = 0; j < WN8; j++)
#pragma unroll
            for (int k = 0; k < 4; k++) acc[i][j][k] = 0.f;

    // ldmatrix per-lane address components
    int a_row = lane & 15, a_ch = lane >> 4;                     // A x4 mapping
    int b_row = ((lane >> 4) << 3) + (lane & 7), b_ch = (lane >> 3) & 1;  // B x4

    load_chunk(0, 0); CP_COMMIT();
    if (nc > 1) { load_chunk(1, 1); CP_COMMIT(); }

    for (int c = 0; c < nc; c++) {
        int s = c & 1;
        if (c + 1 < nc) CP_WAIT1(); else CP_WAIT0();
        __syncthreads();

        uint32_t sAh_ = sb + s * STG;
        uint32_t sAl_ = sAh_ + ATB;
        uint32_t sBh_ = sAh_ + 2 * ATB;
        uint32_t sBl_ = sBh_ + BTB;

#pragma unroll
        for (int kk = 0; kk < 2; kk++) {
            uint32_t ah[4][4], al_[4][4];
#pragma unroll
            for (int mt = 0; mt < 4; mt++) {
                uint32_t off = SWZ(wm * 64 + mt * 16 + a_row, 2 * kk + a_ch);
                ldm_x4(ah[mt],  sAh_ + off);
                ldm_x4(al_[mt], sAl_ + off);
            }
#pragma unroll
            for (int ntp = 0; ntp < WN8 / 2; ntp++) {
                uint32_t boff = SWZ(wn * WN + ntp * 16 + b_row, 2 * kk + b_ch);
                uint32_t bh[4], bl[4];
                ldm_x4(bh, sBh_ + boff);
                ldm_x4(bl, sBl_ + boff);
#pragma unroll
                for (int mt = 0; mt < 4; mt++) {
                    mma_bf16(acc[mt][2 * ntp],     ah[mt],  bh + 0);
                    mma_bf16(acc[mt][2 * ntp],     ah[mt],  bl + 0);
                    mma_bf16(acc[mt][2 * ntp],     al_[mt], bh + 0);
                    mma_bf16(acc[mt][2 * ntp + 1], ah[mt],  bh + 2);
                    mma_bf16(acc[mt][2 * ntp + 1], ah[mt],  bl + 2);
                    mma_bf16(acc[mt][2 * ntp + 1], al_[mt], bh + 2);
                }
            }
        }
        __syncthreads();
        if (c + 2 < nc) { load_chunk(c + 2, s); CP_COMMIT(); }
    }

    // Epilogue
    long zco = zb * sCo + zi * sCi;
    int mrow = lane >> 2, nc2 = (lane & 3) * 2;
#pragma unroll
    for (int mt = 0; mt < 4; mt++) {
#pragma unroll
        for (int nt = 0; nt < WN8; nt++) {
#pragma unroll
            for (int e = 0; e < 4; e++) {
                int gr = m0 + wm * 64 + mt * 16 + mrow + ((e >> 1) << 3);
                int gn = n0 + wn * WN + nt * 8 + nc2 + (e & 1);
                float v = acc[mt][nt][e] * alpha;
                if (bias) v += bias[gn];
                long off = zco + (long)gr * ldc + gn;
                if (res) v += res[off];
                if (act == 1)      v = fmaxf(v, 0.f);
                else if (act == 2) v = 1.f / (1.f + __expf(-v));
                if (C) C[off] = v;
                if (Ch) {
                    bf h = __float2bfloat16(v);
                    Ch[off] = h;
                    Cl[off] = __float2bfloat16(v - __bfloat162float(h));
                }
            }
        }
    }
}

// ===========================================================================
// Aux kernels
// ===========================================================================
__device__ __forceinline__ float blk_reduce_sum(float v) {
    __shared__ float sh[8];
    int t = threadIdx.x;
#pragma unroll
    for (int o = 16; o; o >>= 1) v += __shfl_down_sync(0xffffffffu, v, o);
    if ((t & 31) == 0) sh[t >> 5] = v;
    __syncthreads();
    if (t < 32) {
        float w = (t < 8) ? sh[t] : 0.f;
#pragma unroll
        for (int o = 4; o; o >>= 1) w += __shfl_down_sync(0xffffffffu, w, o);
        if (t == 0) sh[0] = w;
    }
    __syncthreads();
    float r = sh[0];
    __syncthreads();
    return r;
}
__device__ __forceinline__ float blk_reduce_max(float v) {
    __shared__ float sh[8];
    int t = threadIdx.x;
#pragma unroll
    for (int o = 16; o; o >>= 1) v = fmaxf(v, __shfl_down_sync(0xffffffffu, v, o));
    if ((t & 31) == 0) sh[t >> 5] = v;
    __syncthreads();
    if (t < 32) {
        float w = (t < 8) ? sh[t] : -1e30f;
#pragma unroll
        for (int o = 4; o; o >>= 1) w = fmaxf(w, __shfl_down_sync(0xffffffffu, w, o));
        if (t == 0) sh[0] = w;
    }
    __syncthreads();
    float r = sh[0];
    __syncthreads();
    return r;
}

// LayerNorm with optional fp32 and/or split-bf16 outputs
__global__ void ln_kernel(const float* __restrict__ x, const float* __restrict__ g,
                          const float* __restrict__ b, float* __restrict__ yf,
                          bf* __restrict__ yh, bf* __restrict__ yl, int D)
{
    long row = blockIdx.x;
    const float* xr = x + row * (long)D;
    float s = 0.f;
    for (int i = threadIdx.x; i < D; i += 256) s += xr[i];
    float mean = blk_reduce_sum(s) / (float)D;
    float vs = 0.f;
    for (int i = threadIdx.x; i < D; i += 256) { float d = xr[i] - mean; vs += d * d; }
    float var = blk_reduce_sum(vs) / (float)D;
    float rstd = rsqrtf(var + 1e-5f);
    for (int i = threadIdx.x; i < D; i += 256) {
        float v = (xr[i] - mean) * rstd * g[i] + b[i];
        long o = row * (long)D + i;
        if (yf) yf[o] = v;
        if (yh) {
            bf h = __float2bfloat16(v);
            yh[o] = h;
            yl[o] = __float2bfloat16(v - __bfloat162float(h));
        }
    }
}

// Softmax over rows of 2048, output split bf16
__global__ void softmax_split_kernel(const float* __restrict__ s,
                                     bf* __restrict__ oh, bf* __restrict__ ol)
{
    long row = blockIdx.x;
    const float* p = s + row * 2048L;
    float v[8];
    float m = -1e30f;
#pragma unroll
    for (int l = 0; l < 8; l++) { v[l] = p[threadIdx.x + l * 256]; m = fmaxf(m, v[l]); }
    m = blk_reduce_max(m);
    float sum = 0.f;
#pragma unroll
    for (int l = 0; l < 8; l++) { v[l] = __expf(v[l] - m); sum += v[l]; }
    sum = blk_reduce_sum(sum);
    float inv = 1.f / sum;
#pragma unroll
    for (int l = 0; l < 8; l++) {
        float f = v[l] * inv;
        long o = row * 2048L + threadIdx.x + l * 256;
        bf h = __float2bfloat16(f);
        oh[o] = h;
        ol[o] = __float2bfloat16(f - __bfloat162float(h));
    }
}

// fp32 -> split bf16 (n multiple of 1024)
__global__ void split_kernel(const float* __restrict__ x, bf* __restrict__ h,
                             bf* __restrict__ l, long n)
{
    long i = ((long)blockIdx.x * 256 + threadIdx.x) * 4;
    if (i < n) {
        float4 v = *(const float4*)(x + i);
        float a[4] = {v.x, v.y, v.z, v.w};
#pragma unroll
        for (int j = 0; j < 4; j++) {
            bf hh = __float2bfloat16(a[j]);
            h[i + j] = hh;
            l[i + j] = __float2bfloat16(a[j] - __bfloat162float(hh));
        }
    }
}

// Weight transpose + split: W[K,N] fp32 -> Th/Tl [N,K] bf16
__global__ void wtrans_kernel(const float* __restrict__ W, bf* __restrict__ Th,
                              bf* __restrict__ Tl, int K, int N)
{
    __shared__ float t[32][33];
    int k0 = blockIdx.x * 32, n0 = blockIdx.y * 32;
    int x = threadIdx.x, y = threadIdx.y;   // 32 x 8
#pragma unroll
    for (int i = 0; i < 32; i += 8)
        t[y + i][x] = W[(long)(k0 + y + i) * N + n0 + x];
    __syncthreads();
#pragma unroll
    for (int i = 0; i < 32; i += 8) {
        float v = t[x][y + i];
        bf h = __float2bfloat16(v);
        long o = (long)(n0 + y + i) * K + k0 + x;
        Th[o] = h;
        Tl[o] = __float2bfloat16(v - __bfloat162float(h));
    }
}

// V transpose (bf16): qkv[:,1024+h*64 : +64] -> vt[z][64][2048]
__global__ void vtrans_kernel(const bf* __restrict__ qh, const bf* __restrict__ ql,
                              bf* __restrict__ vh, bf* __restrict__ vl)
{
    __shared__ bf th[32][33], tl[32][33];
    int z = blockIdx.z; int b = z >> 3, hh = z & 7;
    int k0 = blockIdx.x * 32, n0 = blockIdx.y * 32;
    int x = threadIdx.x, y = threadIdx.y;
    const long ibase = (long)b * 2048 * 1536 + 1024 + hh * 64;
#pragma unroll
    for (int i = 0; i < 32; i += 8) {
        long go = ibase + (long)(k0 + y + i) * 1536 + n0 + x;
        th[y + i][x] = qh[go];
        tl[y + i][x] = ql[go];
    }
    __syncthreads();
    const long obase = (long)z * 64 * 2048;
#pragma unroll
    for (int i = 0; i < 32; i += 8) {
        long o = obase + (long)(n0 + y + i) * 2048 + k0 + x;
        vh[o] = th[x][y + i];
        vl[o] = tl[x][y + i];
    }
}

// Pool: pooled[b][h] = mean_s hidden[b][s][h]
__global__ void pool_mean_kernel(const float* __restrict__ hs, float* __restrict__ pooled)
{
    int b = blockIdx.y;
    int h = blockIdx.x * 256 + threadIdx.x;
    const float* p = hs + (long)b * SS * HH + h;
    float sum = 0.f;
    for (int s = 0; s < SS; s++) sum += p[(long)s * HH];
    pooled[b * HH + h] = sum * (1.f / SS);
}

// Complexity assessor MLP (tiny)
__global__ void ca_kernel(const float* __restrict__ pooled,
                          const float* __restrict__ w1, const float* __restrict__ b1,
                          const float* __restrict__ w2, const float* __restrict__ b2,
                          const float* __restrict__ w3, const float* __restrict__ b3,
                          float* __restrict__ scores_out)
{
    __shared__ float h1[BB][256];
    __shared__ float h2[BB][32];
    int t = threadIdx.x;
    for (int b = 0; b < BB; b++) {
        float acc = b1[t];
        for (int k = 0; k < HH; k++) acc = fmaf(pooled[b * HH + k], w1[k * 256 + t], acc);
        h1[b][t] = fmaxf(acc, 0.f);
    }
    __syncthreads();
    if (t < 32) {
        for (int b = 0; b < BB; b++) {
            float acc = b2[t];
            for (int k = 0; k < 256; k++) acc = fmaf(h1[b][k], w2[k * 32 + t], acc);
            h2[b][t] = fmaxf(acc, 0.f);
        }
    }
    __syncthreads();
    if (t < BB) {
        float acc = b3[0];
        for (int k = 0; k < 32; k++) acc = fmaf(h2[t][k], w3[k], acc);
        scores_out[t] = 1.f / (1.f + expf(-acc));
    }
}

// out = hidden + g * reasoned
__global__ void gate_out_kernel(const float* __restrict__ hs, const float* __restrict__ g,
                                const float* __restrict__ reasoned, float* __restrict__ out,
                                long n)
{
    long i = (long)blockIdx.x * 256 + threadIdx.x;
    if (i < n) out[i] = hs[i] + g[i] * reasoned[i];
}

// ===========================================================================
// Host
// ===========================================================================
template <int BN>
static void launch_gemm(const bf* Ah, const bf* Al, const bf* Bh, const bf* Bl,
                        const float* bias, const float* res,
                        float* C, bf* Ch, bf* Cl,
                        int M, int N, int K, int lda, int ldb, int ldc,
                        long sAo, long sAi, long sBo, long sBi, long sCo, long sCi,
                        int Z, int zdiv, float alpha, int act)
{
    int sm = 2 * (2 * 128 * 64 + 2 * BN * 64);
    cudaFuncSetAttribute(gemm_tc_kernel<BN>, cudaFuncAttributeMaxDynamicSharedMemorySize, sm);
    dim3 grid(N / BN, M / 128, Z);
    gemm_tc_kernel<BN><<<grid, 256, sm>>>(Ah, Al, Bh, Bl, bias, res, C, Ch, Cl,
        K, lda, ldb, ldc, sAo, sAi, sBo, sBi, sCo, sCi, zdiv, alpha, act);
}

#define SYM(p, s) do { void* _t; cudaGetSymbolAddress(&_t, s); p = (decltype(p))_t; } while (0)

extern "C" void kernel_launch(void* const* d_in, const int* in_sizes, int n_in,
                              void* d_out, int out_size)
{
    const float* hs    = (const float*)d_in[0];
    const float* ca_w1 = (const float*)d_in[1];
    const float* ca_b1 = (const float*)d_in[2];
    const float* ca_w2 = (const float*)d_in[3];
    const float* ca_b2 = (const float*)d_in[4];
    const float* ca_w3 = (const float*)d_in[5];
    const float* ca_b3 = (const float*)d_in[6];
    const float* rp_w  = (const float*)d_in[7];
    const float* rp_b  = (const float*)d_in[8];
    const float* rn_g  = (const float*)d_in[9];
    const float* rn_b  = (const float*)d_in[10];
    const float* ln1_g = (const float*)d_in[11];
    const float* ln1_b = (const float*)d_in[12];
    const float* wqkv  = (const float*)d_in[13];
    const float* bqkv  = (const float*)d_in[14];
    const float* wo    = (const float*)d_in[15];
    const float* bo    = (const float*)d_in[16];
    const float* ln2_g = (const float*)d_in[17];
    const float* ln2_b = (const float*)d_in[18];
    const float* ff1_w = (const float*)d_in[19];
    const float* ff1_b = (const float*)d_in[20];
    const float* ff2_w = (const float*)d_in[21];
    const float* ff2_b = (const float*)d_in[22];
    const float* op_w  = (const float*)d_in[23];
    const float* op_b  = (const float*)d_in[24];
    const float* on_g  = (const float*)d_in[25];
    const float* on_b  = (const float*)d_in[26];
    const float* gw1   = (const float*)d_in[27];
    const float* gb1   = (const float*)d_in[28];
    const float* gw2   = (const float*)d_in[29];
    const float* gb2   = (const float*)d_in[30];

    float* out = (float*)d_out;
    float* cs  = out + NTOK * HH;

    float *pooled, *r, *sc, *tmpf, *g, *reason;
    SYM(pooled, d_pooled); SYM(r, d_r); SYM(sc, d_sc);
    SYM(tmpf, d_tmpf); SYM(g, d_g); SYM(reason, d_reason);
    bf *hs_h, *hs_l, *y_h, *y_l, *qkv_h, *qkv_l, *attn_h, *attn_l, *vt_h, *vt_l;
    bf *o_h, *o_l, *ff_h, *ff_l, *rs_h, *rs_l, *re_h, *re_l, *t2_h, *t2_l;
    SYM(hs_h, d_hs_h); SYM(hs_l, d_hs_l); SYM(y_h, d_y_h); SYM(y_l, d_y_l);
    SYM(qkv_h, d_qkv_h); SYM(qkv_l, d_qkv_l);
    SYM(attn_h, d_attn_h); SYM(attn_l, d_attn_l);
    SYM(vt_h, d_vt_h); SYM(vt_l, d_vt_l);
    SYM(o_h, d_o_h); SYM(o_l, d_o_l); SYM(ff_h, d_ff_h); SYM(ff_l, d_ff_l);
    SYM(rs_h, d_rs_h); SYM(rs_l, d_rs_l); SYM(re_h, d_re_h); SYM(re_l, d_re_l);
    SYM(t2_h, d_t2_h); SYM(t2_l, d_t2_l);
    bf *rpT_h, *rpT_l, *qkvT_h, *qkvT_l, *woT_h, *woT_l, *ff1T_h, *ff1T_l;
    bf *ff2T_h, *ff2T_l, *opT_h, *opT_l, *g1T_h, *g1T_l, *g2T_h, *g2T_l;
    SYM(rpT_h, d_rpT_h); SYM(rpT_l, d_rpT_l); SYM(qkvT_h, d_qkvT_h); SYM(qkvT_l, d_qkvT_l);
    SYM(woT_h, d_woT_h); SYM(woT_l, d_woT_l); SYM(ff1T_h, d_ff1T_h); SYM(ff1T_l, d_ff1T_l);
    SYM(ff2T_h, d_ff2T_h); SYM(ff2T_l, d_ff2T_l); SYM(opT_h, d_opT_h); SYM(opT_l, d_opT_l);
    SYM(g1T_h, d_g1T_h); SYM(g1T_l, d_g1T_l); SYM(g2T_h, d_g2T_h); SYM(g2T_l, d_g2T_l);

    // -- weight transpose + split (per launch; cheap) --
    auto wt = [&](const float* W, bf* Th, bf* Tl, int K, int N) {
        wtrans_kernel<<<dim3(K / 32, N / 32), dim3(32, 8)>>>(W, Th, Tl, K, N);
    };
    wt(rp_w,  rpT_h,  rpT_l,  1024, 512);
    wt(wqkv,  qkvT_h, qkvT_l, 512,  1536);
    wt(wo,    woT_h,  woT_l,  512,  512);
    wt(ff1_w, ff1T_h, ff1T_l, 512,  2048);
    wt(ff2_w, ff2T_h, ff2T_l, 2048, 512);
    wt(op_w,  opT_h,  opT_l,  512,  1024);
    wt(gw1,   g1T_h,  g1T_l,  2048, 1024);
    wt(gw2,   g2T_h,  g2T_l,  1024, 1024);

    // -- complexity assessor --
    pool_mean_kernel<<<dim3(HH / 256, BB), 256>>>(hs, pooled);
    ca_kernel<<<1, 256>>>(pooled, ca_w1, ca_b1, ca_w2, ca_b2, ca_w3, ca_b3, cs);

    // -- split hidden states --
    split_kernel<<<(int)(NTOK * HH / 4 / 256), 256>>>(hs, hs_h, hs_l, NTOK * HH);

    // -- reasoning proj + pre-norm --
    launch_gemm<128>(hs_h, hs_l, rpT_h, rpT_l, rp_b, nullptr, r, nullptr, nullptr,
                     8192, 512, 1024, 1024, 1024, 512, 0, 0, 0, 0, 0, 0, 1, 1, 1.f, 0);
    ln_kernel<<<8192, 256>>>(r, rn_g, rn_b, r, nullptr, nullptr, 512);

    // -- attention --
    ln_kernel<<<8192, 256>>>(r, ln1_g, ln1_b, nullptr, y_h, y_l, 512);
    launch_gemm<128>(y_h, y_l, qkvT_h, qkvT_l, bqkv, nullptr, nullptr, qkv_h, qkv_l,
                     8192, 1536, 512, 512, 512, 1536, 0, 0, 0, 0, 0, 0, 1, 1, 1.f, 0);
    vtrans_kernel<<<dim3(64, 2, 32), dim3(32, 8)>>>(qkv_h, qkv_l, vt_h, vt_l);
    // scores = (Q @ K^T) / 8
    launch_gemm<128>(qkv_h, qkv_l, qkv_h + 512, qkv_l + 512, nullptr, nullptr,
                     sc, nullptr, nullptr, 2048, 2048, 64, 1536, 1536, 2048,
                     2048L * 1536, 64, 2048L * 1536, 64,
                     8L * SS * SS, (long)SS * SS, BB * NHEAD, NHEAD, 0.125f, 0);
    softmax_split_kernel<<<BB * NHEAD * SS, 256>>>(sc, attn_h, attn_l);
    // o = attn @ V
    launch_gemm<64>(attn_h, attn_l, vt_h, vt_l, nullptr, nullptr,
                    nullptr, o_h, o_l, 2048, 64, 2048, 2048, 2048, 512,
                    8L * SS * SS, (long)SS * SS, 8L * 64 * 2048, 64L * 2048,
                    2048L * 512, 64, BB * NHEAD, NHEAD, 1.f, 0);
    // r = r + o @ wo + bo
    launch_gemm<128>(o_h, o_l, woT_h, woT_l, bo, r, r, nullptr, nullptr,
                     8192, 512, 512, 512, 512, 512, 0, 0, 0, 0, 0, 0, 1, 1, 1.f, 0);

    // -- FFN --
    ln_kernel<<<8192, 256>>>(r, ln2_g, ln2_b, nullptr, y_h, y_l, 512);
    launch_gemm<128>(y_h, y_l, ff1T_h, ff1T_l, ff1_b, nullptr, nullptr, ff_h, ff_l,
                     8192, 2048, 512, 512, 512, 2048, 0, 0, 0, 0, 0, 0, 1, 1, 1.f, 1);
    launch_gemm<128>(ff_h, ff_l, ff2T_h, ff2T_l, ff2_b, r, r, nullptr, nullptr,
                     8192, 512, 2048, 2048, 2048, 512, 0, 0, 0, 0, 0, 0, 1, 1, 1.f, 0);

    // -- output projection + norm --
    split_kernel<<<(int)(NTOK * RR / 4 / 256), 256>>>(r, rs_h, rs_l, NTOK * RR);
    launch_gemm<128>(rs_h, rs_l, opT_h, opT_l, op_b, nullptr, tmpf, nullptr, nullptr,
                     8192, 1024, 512, 512, 512, 1024, 0, 0, 0, 0, 0, 0, 1, 1, 1.f, 0);
    ln_kernel<<<8192, 256>>>(tmpf, on_g, on_b, reason, re_h, re_l, 1024);

    // -- integration gate --
    launch_gemm<128>(hs_h, hs_l, g1T_h, g1T_l, gb1, nullptr, tmpf, nullptr, nullptr,
                     8192, 1024, 1024, 1024, 2048, 1024, 0, 0, 0, 0, 0, 0, 1, 1, 1.f, 0);
    launch_gemm<128>(re_h, re_l, g1T_h + 1024, g1T_l + 1024, nullptr, tmpf,
                     nullptr, t2_h, t2_l,
                     8192, 1024, 1024, 1024, 2048, 1024, 0, 0, 0, 0, 0, 0, 1, 1, 1.f, 1);
    launch_gemm<128>(t2_h, t2_l, g2T_h, g2T_l, gb2, nullptr, g, nullptr, nullptr,
                     8192, 1024, 1024, 1024, 1024, 1024, 0, 0, 0, 0, 0, 0, 1, 1, 1.f, 2);

    // -- final blend --
    gate_out_kernel<<<(int)((NTOK * HH + 255) / 256), 256>>>(hs, g, reason, out, NTOK * HH);
}

// round 9
// speedup vs baseline: 3.1108x; 1.1592x over previous
#include <cuda_runtime.h>
#include <cuda_bf16.h>
#include <cstdint>
#include <math.h>

typedef __nv_bfloat16 bf;

// Problem constants
#define BB 4
#define SS 2048
#define HH 1024
#define RR 512
#define NHEAD 8
#define HDIM 64
#define NTOK 8192L   // B*S

// ===========================================================================
// Baseline-PTX helpers (sm_80-era: ldmatrix / mma.sync / cp.async)
// ===========================================================================
__device__ __forceinline__ uint32_t smem_to_u32(const void* p) {
    uint32_t a;
    asm("{ .reg .u64 t; cvta.to.shared.u64 t, %1; cvt.u32.u64 %0, t; }" : "=r"(a) : "l"(p));
    return a;
}
__device__ __forceinline__ void ldm_x4(uint32_t* r, uint32_t addr) {
    asm volatile("ldmatrix.sync.aligned.m8n8.x4.shared.b16 {%0,%1,%2,%3}, [%4];"
                 : "=r"(r[0]), "=r"(r[1]), "=r"(r[2]), "=r"(r[3]) : "r"(addr));
}
__device__ __forceinline__ void mma_bf16(float* d, const uint32_t* a, const uint32_t* b) {
    asm volatile("mma.sync.aligned.m16n8k16.row.col.f32.bf16.bf16.f32 "
                 "{%0,%1,%2,%3}, {%4,%5,%6,%7}, {%8,%9}, {%0,%1,%2,%3};"
                 : "+f"(d[0]), "+f"(d[1]), "+f"(d[2]), "+f"(d[3])
                 : "r"(a[0]), "r"(a[1]), "r"(a[2]), "r"(a[3]), "r"(b[0]), "r"(b[1]));
}
#define CP_ASYNC16(dst, src) \
    asm volatile("cp.async.cg.shared.global [%0], [%1], 16;" :: "r"(dst), "l"(src))
#define CP_COMMIT() asm volatile("cp.async.commit_group;" ::: "memory")
#define CP_WAIT1()  asm volatile("cp.async.wait_group 1;" ::: "memory")
#define CP_WAIT0()  asm volatile("cp.async.wait_group 0;" ::: "memory")

// Swizzled smem offset: rows of 64B (32 bf16), 4x 16B chunks, XOR by (row>>1)&3
#define SWZ(row, c) ((uint32_t)((row) * 64 + (((c) ^ (((row) >> 1) & 3)) << 4)))

// ===========================================================================
// Scratch (static device globals; no allocation allowed)
// ===========================================================================
__device__ float d_pooled[BB * HH];
__device__ float d_r[NTOK * RR];
__device__ float d_tmpf[NTOK * HH];
__device__ float d_reason[NTOK * HH];

__device__ bf d_hs_h[NTOK * HH],  d_hs_l[NTOK * HH];
__device__ bf d_y_h[NTOK * RR],   d_y_l[NTOK * RR];
__device__ bf d_qkv_h[NTOK * 3 * RR], d_qkv_l[NTOK * 3 * RR];
__device__ bf d_vt_h[(long)BB * NHEAD * HDIM * SS], d_vt_l[(long)BB * NHEAD * HDIM * SS];
__device__ bf d_o_h[NTOK * RR],   d_o_l[NTOK * RR];
__device__ bf d_ff_h[NTOK * 4 * RR], d_ff_l[NTOK * 4 * RR];
__device__ bf d_rs_h[NTOK * RR],  d_rs_l[NTOK * RR];
__device__ bf d_re_h[NTOK * HH],  d_re_l[NTOK * HH];
__device__ bf d_t2_h[NTOK * HH],  d_t2_l[NTOK * HH];
// transposed + split weights ([N,K] bf16)
__device__ bf d_rpT_h[RR * HH],       d_rpT_l[RR * HH];
__device__ bf d_qkvT_h[3 * RR * RR],  d_qkvT_l[3 * RR * RR];
__device__ bf d_woT_h[RR * RR],       d_woT_l[RR * RR];
__device__ bf d_ff1T_h[4 * RR * RR],  d_ff1T_l[4 * RR * RR];
__device__ bf d_ff2T_h[RR * 4 * RR],  d_ff2T_l[RR * 4 * RR];
__device__ bf d_opT_h[HH * RR],       d_opT_l[HH * RR];
__device__ bf d_g1T_h[HH * 2 * HH],   d_g1T_l[HH * 2 * HH];
__device__ bf d_g2T_h[HH * HH],       d_g2T_l[HH * HH];

// ===========================================================================
// Warp-MMA split-bf16 GEMM: D = Ah*Bh + Ah*Bl + Al*Bh (fp32 accum, HMMA)
//   act: 0 none, 1 relu, 2 sigmoid, 3 fused gate: C = f1 + sigmoid(v)*f2
// ===========================================================================
template <int BN>
__global__ void __launch_bounds__(256, 2) gemm_tc_kernel(
    const bf* __restrict__ Ah, const bf* __restrict__ Al,
    const bf* __restrict__ Bh, const bf* __restrict__ Bl,
    const float* __restrict__ bias, const float* __restrict__ res,
    const float* __restrict__ f1, const float* __restrict__ f2,
    float* __restrict__ C, bf* __restrict__ Ch, bf* __restrict__ Cl,
    int K, int lda, int ldb, int ldc,
    long sAo, long sAi, long sBo, long sBi, long sCo, long sCi, int zdiv,
    float alpha, int act)
{
    constexpr int WN  = BN / 4;       // warp n extent
    constexpr int WN8 = BN / 32;      // n8 tiles per warp
    constexpr int ATB = 128 * 64;     // 8192 B per A matrix per stage
    constexpr int BTB = BN * 64;      // B matrix bytes per stage
    constexpr int STG = 2 * ATB + 2 * BTB;

    extern __shared__ char smem[];
    uint32_t sb = smem_to_u32(smem);

    int tid = threadIdx.x, wid = tid >> 5, lane = tid & 31;
    int wm = wid & 1, wn = wid >> 1;

    long zb = blockIdx.z / zdiv, zi = blockIdx.z % zdiv;
    int m0 = blockIdx.y * 128, n0 = blockIdx.x * BN;
    const bf* gAh = Ah + zb * sAo + zi * sAi + (long)m0 * lda;
    const bf* gAl = Al + zb * sAo + zi * sAi + (long)m0 * lda;
    const bf* gBh = Bh + zb * sBo + zi * sBi + (long)n0 * ldb;
    const bf* gBl = Bl + zb * sBo + zi * sBi + (long)n0 * ldb;

    const int nc = K >> 5;   // 32-wide K chunks

    auto load_chunk = [&](int c, int s) {
        uint32_t base = sb + s * STG;
        long ko = (long)c << 5;
#pragma unroll
        for (int i = tid; i < 512; i += 256) {          // A: 128 rows x 4 chunks
            int r = i >> 2, q = i & 3;
            long go = (long)r * lda + ko + q * 8;
            uint32_t so = SWZ(r, q);
            CP_ASYNC16(base + so,       gAh + go);
            CP_ASYNC16(base + ATB + so, gAl + go);
        }
#pragma unroll
        for (int i = tid; i < BN * 4; i += 256) {       // B: BN rows x 4 chunks
            int r = i >> 2, q = i & 3;
            long go = (long)r * ldb + ko + q * 8;
            uint32_t so = SWZ(r, q);
            CP_ASYNC16(base + 2 * ATB + so,       gBh + go);
            CP_ASYNC16(base + 2 * ATB + BTB + so, gBl + go);
        }
    };

    float acc[4][WN8][4];
#pragma unroll
    for (int i = 0; i < 4; i++)
#pragma unroll
        for (int j = 0; j < WN8; j++)
#pragma unroll
            for (int k = 0; k < 4; k++) acc[i][j][k] = 0.f;

    // ldmatrix per-lane address components
    int a_row = lane & 15, a_ch = lane >> 4;                     // A x4 mapping
    int b_row = ((lane >> 4) << 3) + (lane & 7), b_ch = (lane >> 3) & 1;  // B x4

    load_chunk(0, 0); CP_COMMIT();
    if (nc > 1) { load_chunk(1, 1); CP_COMMIT(); }

    for (int c = 0; c < nc; c++) {
        int s = c & 1;
        if (c + 1 < nc) CP_WAIT1(); else CP_WAIT0();
        __syncthreads();

        uint32_t sAh_ = sb + s * STG;
        uint32_t sAl_ = sAh_ + ATB;
        uint32_t sBh_ = sAh_ + 2 * ATB;
        uint32_t sBl_ = sBh_ + BTB;

#pragma unroll
        for (int kk = 0; kk < 2; kk++) {
            uint32_t ah[4][4], al_[4][4];
#pragma unroll
            for (int mt = 0; mt < 4; mt++) {
                uint32_t off = SWZ(wm * 64 + mt * 16 + a_row, 2 * kk + a_ch);
                ldm_x4(ah[mt],  sAh_ + off);
                ldm_x4(al_[mt], sAl_ + off);
            }
#pragma unroll
            for (int ntp = 0; ntp < WN8 / 2; ntp++) {
                uint32_t boff = SWZ(wn * WN + ntp * 16 + b_row, 2 * kk + b_ch);
                uint32_t bh[4], bl[4];
                ldm_x4(bh, sBh_ + boff);
                ldm_x4(bl, sBl_ + boff);
#pragma unroll
                for (int mt = 0; mt < 4; mt++) {
                    mma_bf16(acc[mt][2 * ntp],     ah[mt],  bh + 0);
                    mma_bf16(acc[mt][2 * ntp],     ah[mt],  bl + 0);
                    mma_bf16(acc[mt][2 * ntp],     al_[mt], bh + 0);
                    mma_bf16(acc[mt][2 * ntp + 1], ah[mt],  bh + 2);
                    mma_bf16(acc[mt][2 * ntp + 1], ah[mt],  bl + 2);
                    mma_bf16(acc[mt][2 * ntp + 1], al_[mt], bh + 2);
                }
            }
        }
        __syncthreads();
        if (c + 2 < nc) { load_chunk(c + 2, s); CP_COMMIT(); }
    }

    // Epilogue
    long zco = zb * sCo + zi * sCi;
    int mrow = lane >> 2, nc2 = (lane & 3) * 2;
#pragma unroll
    for (int mt = 0; mt < 4; mt++) {
#pragma unroll
        for (int nt = 0; nt < WN8; nt++) {
#pragma unroll
            for (int e = 0; e < 4; e++) {
                int gr = m0 + wm * 64 + mt * 16 + mrow + ((e >> 1) << 3);
                int gn = n0 + wn * WN + nt * 8 + nc2 + (e & 1);
                float v = acc[mt][nt][e] * alpha;
                if (bias) v += bias[gn];
                long off = zco + (long)gr * ldc + gn;
                if (res) v += res[off];
                if (act == 1)      v = fmaxf(v, 0.f);
                else if (act == 2) v = 1.f / (1.f + __expf(-v));
                else if (act == 3) { v = 1.f / (1.f + __expf(-v)); v = f1[off] + v * f2[off]; }
                if (C) C[off] = v;
                if (Ch) {
                    bf h = __float2bfloat16(v);
                    Ch[off] = h;
                    Cl[off] = __float2bfloat16(v - __bfloat162float(h));
                }
            }
        }
    }
}

// ===========================================================================
// FlashAttention-2: per (b,h,128-query tile); split-bf16 QK^T and PV.
//   Q/K from qkv (token rows, stride 1536); V from vt ([z][64][2048]).
//   Output: o_h/o_l [token][512] at head offset.
//   smem: Q(h,l) 32KB + 2 stages x (K h,l 32KB + V h,l 32KB) = 160KB.
// ===========================================================================
#define ADDR8(r, c)  ((uint32_t)((r) * 128 + (((c) ^ ((r) & 7)) << 4)))
#define ADDR16(r, c) ((uint32_t)((r) * 256 + ((((c) & 8) | (((c) & 7) ^ ((r) & 7))) << 4)))

__global__ void __launch_bounds__(256, 1) flash_attn_kernel(
    const bf* __restrict__ qkvh, const bf* __restrict__ qkvl,
    const bf* __restrict__ vth,  const bf* __restrict__ vtl,
    bf* __restrict__ oh, bf* __restrict__ ol)
{
    extern __shared__ char smem[];
    uint32_t sb = smem_to_u32(smem);
    const uint32_t QH = 0, QL = 16384, ST0 = 32768;   // stage: +s*65536: KH,KL,VH,VL (16KB each)

    int tid = threadIdx.x, wid = tid >> 5, lane = tid & 31;
    int z = blockIdx.y, b = z >> 3, hh = z & 7;
    int q0 = blockIdx.x * 128;

    const bf* gQh = qkvh + ((long)b * 2048 + q0) * 1536 + hh * 64;
    const bf* gQl = qkvl + ((long)b * 2048 + q0) * 1536 + hh * 64;
    const bf* gKh = qkvh + (long)b * 2048 * 1536 + 512 + hh * 64;
    const bf* gKl = qkvl + (long)b * 2048 * 1536 + 512 + hh * 64;
    const bf* gVh = vth + (long)z * 64 * 2048;
    const bf* gVl = vtl + (long)z * 64 * 2048;

    auto loadKV = [&](int j, int s) {
        uint32_t st = sb + ST0 + s * 65536;
#pragma unroll
        for (int i = tid; i < 1024; i += 256) {
            int r = i >> 3, c = i & 7;
            long go = (long)(j * 128 + r) * 1536 + c * 8;
            uint32_t so = ADDR8(r, c);
            CP_ASYNC16(st + so,         gKh + go);
            CP_ASYNC16(st + 16384 + so, gKl + go);
        }
#pragma unroll
        for (int i = tid; i < 1024; i += 256) {
            int r = i >> 4, c = i & 15;
            long go = (long)r * 2048 + j * 128 + c * 8;
            uint32_t so = ADDR16(r, c);
            CP_ASYNC16(st + 32768 + so, gVh + go);
            CP_ASYNC16(st + 49152 + so, gVl + go);
        }
    };

    // prologue: Q + stage0 (group 0), stage1 (group 1)
#pragma unroll
    for (int i = tid; i < 1024; i += 256) {
        int r = i >> 3, c = i & 7;
        long go = (long)r * 1536 + c * 8;
        uint32_t so = ADDR8(r, c);
        CP_ASYNC16(sb + QH + so, gQh + go);
        CP_ASYNC16(sb + QL + so, gQl + go);
    }
    loadKV(0, 0); CP_COMMIT();
    loadKV(1, 1); CP_COMMIT();

    int a_row = lane & 15, a_ch = lane >> 4;
    int b_row = ((lane >> 4) << 3) + (lane & 7), b_ch = (lane >> 3) & 1;

    uint32_t qh[4][4], ql[4][4];
    float accO[8][4];
#pragma unroll
    for (int i = 0; i < 8; i++)
#pragma unroll
        for (int e = 0; e < 4; e++) accO[i][e] = 0.f;
    float mrow[2] = {-1e30f, -1e30f}, lrow[2] = {0.f, 0.f};

    for (int j = 0; j < 16; j++) {
        if (j < 15) CP_WAIT1(); else CP_WAIT0();
        __syncthreads();
        if (j == 0) {
#pragma unroll
            for (int kk = 0; kk < 4; kk++) {
                uint32_t off = ADDR8(wid * 16 + a_row, 2 * kk + a_ch);
                ldm_x4(qh[kk], sb + QH + off);
                ldm_x4(ql[kk], sb + QL + off);
            }
        }
        uint32_t st = sb + ST0 + (j & 1) * 65536;

        // S = Q @ K^T : per warp m16 x n128 x k64, 3-product split
        float s[16][4];
#pragma unroll
        for (int i = 0; i < 16; i++)
#pragma unroll
            for (int e = 0; e < 4; e++) s[i][e] = 0.f;
#pragma unroll
        for (int kk = 0; kk < 4; kk++) {
#pragma unroll
            for (int ntp = 0; ntp < 8; ntp++) {
                uint32_t off = ADDR8(ntp * 16 + b_row, 2 * kk + b_ch);
                uint32_t bh[4], bl[4];
                ldm_x4(bh, st + off);
                ldm_x4(bl, st + 16384 + off);
                mma_bf16(s[2 * ntp],     qh[kk], bh + 0);
                mma_bf16(s[2 * ntp],     qh[kk], bl + 0);
                mma_bf16(s[2 * ntp],     ql[kk], bh + 0);
                mma_bf16(s[2 * ntp + 1], qh[kk], bh + 2);
                mma_bf16(s[2 * ntp + 1], qh[kk], bl + 2);
                mma_bf16(s[2 * ntp + 1], ql[kk], bh + 2);
            }
        }
#pragma unroll
        for (int i = 0; i < 16; i++)
#pragma unroll
            for (int e = 0; e < 4; e++) s[i][e] *= 0.125f;

        // online softmax (rows r = wid*16 + lane/4 + 8*h2)
#pragma unroll
        for (int h2 = 0; h2 < 2; h2++) {
            float vm = -1e30f;
#pragma unroll
            for (int nt = 0; nt < 16; nt++)
                vm = fmaxf(vm, fmaxf(s[nt][2 * h2], s[nt][2 * h2 + 1]));
            vm = fmaxf(vm, __shfl_xor_sync(0xffffffffu, vm, 1));
            vm = fmaxf(vm, __shfl_xor_sync(0xffffffffu, vm, 2));
            float mn = fmaxf(mrow[h2], vm);
            float scale = __expf(mrow[h2] - mn);
            mrow[h2] = mn;
            float ps = 0.f;
#pragma unroll
            for (int nt = 0; nt < 16; nt++) {
                float e0 = __expf(s[nt][2 * h2] - mn);
                float e1 = __expf(s[nt][2 * h2 + 1] - mn);
                s[nt][2 * h2] = e0; s[nt][2 * h2 + 1] = e1;
                ps += e0 + e1;
            }
            ps += __shfl_xor_sync(0xffffffffu, ps, 1);
            ps += __shfl_xor_sync(0xffffffffu, ps, 2);
            lrow[h2] = lrow[h2] * scale + ps;
#pragma unroll
            for (int nt2 = 0; nt2 < 8; nt2++) {
                accO[nt2][2 * h2]     *= scale;
                accO[nt2][2 * h2 + 1] *= scale;
            }
        }

        // P @ V : per k16 tile, pack P (C-frag -> A-frag), split bf16
#pragma unroll
        for (int kt = 0; kt < 8; kt++) {
            uint32_t Ph[4], Pl[4];
#pragma unroll
            for (int jj = 0; jj < 4; jj++) {
                float va = s[2 * kt + (jj >> 1)][(jj & 1) * 2];
                float vb = s[2 * kt + (jj >> 1)][(jj & 1) * 2 + 1];
                bf ha = __float2bfloat16(va), hb = __float2bfloat16(vb);
                float ra = va - __bfloat162float(ha), rb = vb - __bfloat162float(hb);
                Ph[jj] = (uint32_t)__bfloat16_as_ushort(ha) |
                         ((uint32_t)__bfloat16_as_ushort(hb) << 16);
                Pl[jj] = (uint32_t)__bfloat16_as_ushort(__float2bfloat16(ra)) |
                         ((uint32_t)__bfloat16_as_ushort(__float2bfloat16(rb)) << 16);
            }
#pragma unroll
            for (int np = 0; np < 4; np++) {
                uint32_t off = ADDR16(np * 16 + b_row, 2 * kt + b_ch);
                uint32_t vh[4], vl[4];
                ldm_x4(vh, st + 32768 + off);
                ldm_x4(vl, st + 49152 + off);
                mma_bf16(accO[2 * np],     Ph, vh + 0);
                mma_bf16(accO[2 * np],     Ph, vl + 0);
                mma_bf16(accO[2 * np],     Pl, vh + 0);
                mma_bf16(accO[2 * np + 1], Ph, vh + 2);
                mma_bf16(accO[2 * np + 1], Ph, vl + 2);
                mma_bf16(accO[2 * np + 1], Pl, vh + 2);
            }
        }
        __syncthreads();
        if (j + 2 < 16) { loadKV(j + 2, j & 1); CP_COMMIT(); }
    }

    // write O = accO / l  (split bf16)
    float inv0 = 1.f / lrow[0], inv1 = 1.f / lrow[1];
    long tok0 = (long)b * 2048 + q0 + wid * 16 + (lane >> 2);
    int colb = hh * 64 + (lane & 3) * 2;
#pragma unroll
    for (int nt2 = 0; nt2 < 8; nt2++) {
#pragma unroll
        for (int e = 0; e < 4; e++) {
            long row = tok0 + 8 * (e >> 1);
            int col = colb + nt2 * 8 + (e & 1);
            float v = accO[nt2][e] * ((e >> 1) ? inv1 : inv0);
            bf h = __float2bfloat16(v);
            long off = row * 512 + col;
            oh[off] = h;
            ol[off] = __float2bfloat16(v - __bfloat162float(h));
        }
    }
}

// ===========================================================================
// Aux kernels
// ===========================================================================
__device__ __forceinline__ float blk_reduce_sum(float v) {
    __shared__ float sh[8];
    int t = threadIdx.x;
#pragma unroll
    for (int o = 16; o; o >>= 1) v += __shfl_down_sync(0xffffffffu, v, o);
    if ((t & 31) == 0) sh[t >> 5] = v;
    __syncthreads();
    if (t < 32) {
        float w = (t < 8) ? sh[t] : 0.f;
#pragma unroll
        for (int o = 4; o; o >>= 1) w += __shfl_down_sync(0xffffffffu, w, o);
        if (t == 0) sh[0] = w;
    }
    __syncthreads();
    float r = sh[0];
    __syncthreads();
    return r;
}

// LayerNorm with optional fp32 and/or split-bf16 outputs
__global__ void ln_kernel(const float* __restrict__ x, const float* __restrict__ g,
                          const float* __restrict__ b, float* __restrict__ yf,
                          bf* __restrict__ yh, bf* __restrict__ yl, int D)
{
    long row = blockIdx.x;
    const float* xr = x + row * (long)D;
    float s = 0.f;
    for (int i = threadIdx.x; i < D; i += 256) s += xr[i];
    float mean = blk_reduce_sum(s) / (float)D;
    float vs = 0.f;
    for (int i = threadIdx.x; i < D; i += 256) { float d = xr[i] - mean; vs += d * d; }
    float var = blk_reduce_sum(vs) / (float)D;
    float rstd = rsqrtf(var + 1e-5f);
    for (int i = threadIdx.x; i < D; i += 256) {
        float v = (xr[i] - mean) * rstd * g[i] + b[i];
        long o = row * (long)D + i;
        if (yf) yf[o] = v;
        if (yh) {
            bf h = __float2bfloat16(v);
            yh[o] = h;
            yl[o] = __float2bfloat16(v - __bfloat162float(h));
        }
    }
}

// fp32 -> split bf16 (n multiple of 1024)
__global__ void split_kernel(const float* __restrict__ x, bf* __restrict__ h,
                             bf* __restrict__ l, long n)
{
    long i = ((long)blockIdx.x * 256 + threadIdx.x) * 4;
    if (i < n) {
        float4 v = *(const float4*)(x + i);
        float a[4] = {v.x, v.y, v.z, v.w};
#pragma unroll
        for (int j = 0; j < 4; j++) {
            bf hh = __float2bfloat16(a[j]);
            h[i + j] = hh;
            l[i + j] = __float2bfloat16(a[j] - __bfloat162float(hh));
        }
    }
}

// Weight transpose + split: W[K,N] fp32 -> Th/Tl [N,K] bf16
__global__ void wtrans_kernel(const float* __restrict__ W, bf* __restrict__ Th,
                              bf* __restrict__ Tl, int K, int N)
{
    __shared__ float t[32][33];
    int k0 = blockIdx.x * 32, n0 = blockIdx.y * 32;
    int x = threadIdx.x, y = threadIdx.y;   // 32 x 8
#pragma unroll
    for (int i = 0; i < 32; i += 8)
        t[y + i][x] = W[(long)(k0 + y + i) * N + n0 + x];
    __syncthreads();
#pragma unroll
    for (int i = 0; i < 32; i += 8) {
        float v = t[x][y + i];
        bf h = __float2bfloat16(v);
        long o = (long)(n0 + y + i) * K + k0 + x;
        Th[o] = h;
        Tl[o] = __float2bfloat16(v - __bfloat162float(h));
    }
}

// V transpose (bf16): qkv[:,1024+h*64 : +64] -> vt[z][64][2048]
__global__ void vtrans_kernel(const bf* __restrict__ qh, const bf* __restrict__ ql,
                              bf* __restrict__ vh, bf* __restrict__ vl)
{
    __shared__ bf th[32][33], tl[32][33];
    int z = blockIdx.z; int b = z >> 3, hh = z & 7;
    int k0 = blockIdx.x * 32, n0 = blockIdx.y * 32;
    int x = threadIdx.x, y = threadIdx.y;
    const long ibase = (long)b * 2048 * 1536 + 1024 + hh * 64;
#pragma unroll
    for (int i = 0; i < 32; i += 8) {
        long go = ibase + (long)(k0 + y + i) * 1536 + n0 + x;
        th[y + i][x] = qh[go];
        tl[y + i][x] = ql[go];
    }
    __syncthreads();
    const long obase = (long)z * 64 * 2048;
#pragma unroll
    for (int i = 0; i < 32; i += 8) {
        long o = obase + (long)(n0 + y + i) * 2048 + k0 + x;
        vh[o] = th[x][y + i];
        vl[o] = tl[x][y + i];
    }
}

// Pool: pooled[b][h] = mean_s hidden[b][s][h]
__global__ void pool_mean_kernel(const float* __restrict__ hs, float* __restrict__ pooled)
{
    int b = blockIdx.y;
    int h = blockIdx.x * 256 + threadIdx.x;
    const float* p = hs + (long)b * SS * HH + h;
    float sum = 0.f;
    for (int s = 0; s < SS; s++) sum += p[(long)s * HH];
    pooled[b * HH + h] = sum * (1.f / SS);
}

// Complexity assessor MLP (tiny)
__global__ void ca_kernel(const float* __restrict__ pooled,
                          const float* __restrict__ w1, const float* __restrict__ b1,
                          const float* __restrict__ w2, const float* __restrict__ b2,
                          const float* __restrict__ w3, const float* __restrict__ b3,
                          float* __restrict__ scores_out)
{
    __shared__ float h1[BB][256];
    __shared__ float h2[BB][32];
    int t = threadIdx.x;
    for (int b = 0; b < BB; b++) {
        float acc = b1[t];
        for (int k = 0; k < HH; k++) acc = fmaf(pooled[b * HH + k], w1[k * 256 + t], acc);
        h1[b][t] = fmaxf(acc, 0.f);
    }
    __syncthreads();
    if (t < 32) {
        for (int b = 0; b < BB; b++) {
            float acc = b2[t];
            for (int k = 0; k < 256; k++) acc = fmaf(h1[b][k], w2[k * 32 + t], acc);
            h2[b][t] = fmaxf(acc, 0.f);
        }
    }
    __syncthreads();
    if (t < BB) {
        float acc = b3[0];
        for (int k = 0; k < 32; k++) acc = fmaf(h2[t][k], w3[k], acc);
        scores_out[t] = 1.f / (1.f + expf(-acc));
    }
}

// ===========================================================================
// Host
// ===========================================================================
template <int BN>
static void launch_gemm(const bf* Ah, const bf* Al, const bf* Bh, const bf* Bl,
                        const float* bias, const float* res,
                        const float* f1, const float* f2,
                        float* C, bf* Ch, bf* Cl,
                        int M, int N, int K, int lda, int ldb, int ldc,
                        long sAo, long sAi, long sBo, long sBi, long sCo, long sCi,
                        int Z, int zdiv, float alpha, int act)
{
    int sm = 2 * (2 * 128 * 64 + 2 * BN * 64);
    cudaFuncSetAttribute(gemm_tc_kernel<BN>, cudaFuncAttributeMaxDynamicSharedMemorySize, sm);
    dim3 grid(N / BN, M / 128, Z);
    gemm_tc_kernel<BN><<<grid, 256, sm>>>(Ah, Al, Bh, Bl, bias, res, f1, f2, C, Ch, Cl,
        K, lda, ldb, ldc, sAo, sAi, sBo, sBi, sCo, sCi, zdiv, alpha, act);
}

#define SYM(p, s) do { void* _t; cudaGetSymbolAddress(&_t, s); p = (decltype(p))_t; } while (0)

extern "C" void kernel_launch(void* const* d_in, const int* in_sizes, int n_in,
                              void* d_out, int out_size)
{
    const float* hs    = (const float*)d_in[0];
    const float* ca_w1 = (const float*)d_in[1];
    const float* ca_b1 = (const float*)d_in[2];
    const float* ca_w2 = (const float*)d_in[3];
    const float* ca_b2 = (const float*)d_in[4];
    const float* ca_w3 = (const float*)d_in[5];
    const float* ca_b3 = (const float*)d_in[6];
    const float* rp_w  = (const float*)d_in[7];
    const float* rp_b  = (const float*)d_in[8];
    const float* rn_g  = (const float*)d_in[9];
    const float* rn_b  = (const float*)d_in[10];
    const float* ln1_g = (const float*)d_in[11];
    const float* ln1_b = (const float*)d_in[12];
    const float* wqkv  = (const float*)d_in[13];
    const float* bqkv  = (const float*)d_in[14];
    const float* wo    = (const float*)d_in[15];
    const float* bo    = (const float*)d_in[16];
    const float* ln2_g = (const float*)d_in[17];
    const float* ln2_b = (const float*)d_in[18];
    const float* ff1_w = (const float*)d_in[19];
    const float* ff1_b = (const float*)d_in[20];
    const float* ff2_w = (const float*)d_in[21];
    const float* ff2_b = (const float*)d_in[22];
    const float* op_w  = (const float*)d_in[23];
    const float* op_b  = (const float*)d_in[24];
    const float* on_g  = (const float*)d_in[25];
    const float* on_b  = (const float*)d_in[26];
    const float* gw1   = (const float*)d_in[27];
    const float* gb1   = (const float*)d_in[28];
    const float* gw2   = (const float*)d_in[29];
    const float* gb2   = (const float*)d_in[30];

    float* out = (float*)d_out;
    float* cs  = out + NTOK * HH;

    float *pooled, *r, *tmpf, *reason;
    SYM(pooled, d_pooled); SYM(r, d_r); SYM(tmpf, d_tmpf); SYM(reason, d_reason);
    bf *hs_h, *hs_l, *y_h, *y_l, *qkv_h, *qkv_l, *vt_h, *vt_l;
    bf *o_h, *o_l, *ff_h, *ff_l, *rs_h, *rs_l, *re_h, *re_l, *t2_h, *t2_l;
    SYM(hs_h, d_hs_h); SYM(hs_l, d_hs_l); SYM(y_h, d_y_h); SYM(y_l, d_y_l);
    SYM(qkv_h, d_qkv_h); SYM(qkv_l, d_qkv_l);
    SYM(vt_h, d_vt_h); SYM(vt_l, d_vt_l);
    SYM(o_h, d_o_h); SYM(o_l, d_o_l); SYM(ff_h, d_ff_h); SYM(ff_l, d_ff_l);
    SYM(rs_h, d_rs_h); SYM(rs_l, d_rs_l); SYM(re_h, d_re_h); SYM(re_l, d_re_l);
    SYM(t2_h, d_t2_h); SYM(t2_l, d_t2_l);
    bf *rpT_h, *rpT_l, *qkvT_h, *qkvT_l, *woT_h, *woT_l, *ff1T_h, *ff1T_l;
    bf *ff2T_h, *ff2T_l, *opT_h, *opT_l, *g1T_h, *g1T_l, *g2T_h, *g2T_l;
    SYM(rpT_h, d_rpT_h); SYM(rpT_l, d_rpT_l); SYM(qkvT_h, d_qkvT_h); SYM(qkvT_l, d_qkvT_l);
    SYM(woT_h, d_woT_h); SYM(woT_l, d_woT_l); SYM(ff1T_h, d_ff1T_h); SYM(ff1T_l, d_ff1T_l);
    SYM(ff2T_h, d_ff2T_h); SYM(ff2T_l, d_ff2T_l); SYM(opT_h, d_opT_h); SYM(opT_l, d_opT_l);
    SYM(g1T_h, d_g1T_h); SYM(g1T_l, d_g1T_l); SYM(g2T_h, d_g2T_h); SYM(g2T_l, d_g2T_l);

    // -- weight transpose + split --
    auto wt = [&](const float* W, bf* Th, bf* Tl, int K, int N) {
        wtrans_kernel<<<dim3(K / 32, N / 32), dim3(32, 8)>>>(W, Th, Tl, K, N);
    };
    wt(rp_w,  rpT_h,  rpT_l,  1024, 512);
    wt(wqkv,  qkvT_h, qkvT_l, 512,  1536);
    wt(wo,    woT_h,  woT_l,  512,  512);
    wt(ff1_w, ff1T_h, ff1T_l, 512,  2048);
    wt(ff2_w, ff2T_h, ff2T_l, 2048, 512);
    wt(op_w,  opT_h,  opT_l,  512,  1024);
    wt(gw1,   g1T_h,  g1T_l,  2048, 1024);
    wt(gw2,   g2T_h,  g2T_l,  1024, 1024);

    // -- complexity assessor --
    pool_mean_kernel<<<dim3(HH / 256, BB), 256>>>(hs, pooled);
    ca_kernel<<<1, 256>>>(pooled, ca_w1, ca_b1, ca_w2, ca_b2, ca_w3, ca_b3, cs);

    // -- split hidden states --
    split_kernel<<<(int)(NTOK * HH / 4 / 256), 256>>>(hs, hs_h, hs_l, NTOK * HH);

    // -- reasoning proj + pre-norm --
    launch_gemm<128>(hs_h, hs_l, rpT_h, rpT_l, rp_b, nullptr, nullptr, nullptr,
                     r, nullptr, nullptr,
                     8192, 512, 1024, 1024, 1024, 512, 0, 0, 0, 0, 0, 0, 1, 1, 1.f, 0);
    ln_kernel<<<8192, 256>>>(r, rn_g, rn_b, r, nullptr, nullptr, 512);

    // -- attention --
    ln_kernel<<<8192, 256>>>(r, ln1_g, ln1_b, nullptr, y_h, y_l, 512);
    launch_gemm<128>(y_h, y_l, qkvT_h, qkvT_l, bqkv, nullptr, nullptr, nullptr,
                     nullptr, qkv_h, qkv_l,
                     8192, 1536, 512, 512, 512, 1536, 0, 0, 0, 0, 0, 0, 1, 1, 1.f, 0);
    vtrans_kernel<<<dim3(64, 2, 32), dim3(32, 8)>>>(qkv_h, qkv_l, vt_h, vt_l);
    // fused flash attention (QK^T + softmax + @V)
    {
        cudaFuncSetAttribute(flash_attn_kernel,
                             cudaFuncAttributeMaxDynamicSharedMemorySize, 163840);
        dim3 grid(16, 32);
        flash_attn_kernel<<<grid, 256, 163840>>>(qkv_h, qkv_l, vt_h, vt_l, o_h, o_l);
    }
    // r = r + o @ wo + bo
    launch_gemm<128>(o_h, o_l, woT_h, woT_l, bo, r, nullptr, nullptr,
                     r, nullptr, nullptr,
                     8192, 512, 512, 512, 512, 512, 0, 0, 0, 0, 0, 0, 1, 1, 1.f, 0);

    // -- FFN --
    ln_kernel<<<8192, 256>>>(r, ln2_g, ln2_b, nullptr, y_h, y_l, 512);
    launch_gemm<128>(y_h, y_l, ff1T_h, ff1T_l, ff1_b, nullptr, nullptr, nullptr,
                     nullptr, ff_h, ff_l,
                     8192, 2048, 512, 512, 512, 2048, 0, 0, 0, 0, 0, 0, 1, 1, 1.f, 1);
    launch_gemm<128>(ff_h, ff_l, ff2T_h, ff2T_l, ff2_b, r, nullptr, nullptr,
                     r, nullptr, nullptr,
                     8192, 512, 2048, 2048, 2048, 512, 0, 0, 0, 0, 0, 0, 1, 1, 1.f, 0);

    // -- output projection + norm --
    split_kernel<<<(int)(NTOK * RR / 4 / 256), 256>>>(r, rs_h, rs_l, NTOK * RR);
    launch_gemm<128>(rs_h, rs_l, opT_h, opT_l, op_b, nullptr, nullptr, nullptr,
                     tmpf, nullptr, nullptr,
                     8192, 1024, 512, 512, 512, 1024, 0, 0, 0, 0, 0, 0, 1, 1, 1.f, 0);
    ln_kernel<<<8192, 256>>>(tmpf, on_g, on_b, reason, re_h, re_l, 1024);

    // -- integration gate (final blend fused into last GEMM) --
    launch_gemm<128>(hs_h, hs_l, g1T_h, g1T_l, gb1, nullptr, nullptr, nullptr,
                     tmpf, nullptr, nullptr,
                     8192, 1024, 1024, 1024, 2048, 1024, 0, 0, 0, 0, 0, 0, 1, 1, 1.f, 0);
    launch_gemm<128>(re_h, re_l, g1T_h + 1024, g1T_l + 1024, nullptr, tmpf, nullptr, nullptr,
                     nullptr, t2_h, t2_l,
                     8192, 1024, 1024, 1024, 2048, 1024, 0, 0, 0, 0, 0, 0, 1, 1, 1.f, 1);
    launch_gemm<128>(t2_h, t2_l, g2T_h, g2T_l, gb2, nullptr, hs, reason,
                     out, nullptr, nullptr,
                     8192, 1024, 1024, 1024, 1024, 1024, 0, 0, 0, 0, 0, 0, 1, 1, 1.f, 3);
}